// round 12
// baseline (speedup 1.0000x reference)
#include <cuda_runtime.h>
#include <math.h>

// N=100000, E=1280000, IN_D=256, FEAT=HID=OUT=64
#define NMAX 100000
#define EMAX 1280000
#define NEG_SLOPE 0.2f

// ---------------- scratch ----------------
__device__ float g_hA[NMAX * 64];
__device__ float g_hB[NMAX * 64];
__device__ float g_lin[NMAX * 64];
__device__ float g_es[NMAX];
__device__ float g_ed[NMAX];
__device__ int   g_deg[NMAX];
__device__ int   g_cur[NMAX];
__device__ int   g_rowptr[NMAX + 1];
__device__ int   g_col[EMAX];

__device__ __forceinline__ float leaky(float x) { return x > 0.f ? x : NEG_SLOPE * x; }

typedef unsigned long long ull;
__device__ __forceinline__ void fma2(ull& d, ull a, ull b) {
    asm("fma.rn.f32x2 %0, %1, %2, %0;" : "+l"(d) : "l"(a), "l"(b));
}
__device__ __forceinline__ ull pack2(float lo, float hi) {
    ull r;
    asm("mov.b64 %0, {%1, %2};" : "=l"(r) : "f"(lo), "f"(hi));
    return r;
}
__device__ __forceinline__ float2 unpack2(ull v) {
    float2 f;
    asm("mov.b64 {%0, %1}, %2;" : "=f"(f.x), "=f"(f.y) : "l"(v));
    return f;
}

// ---------------- CSR build ----------------
__global__ void k_hist(const int* __restrict__ dst, int e) {
    int i = blockIdx.x * blockDim.x + threadIdx.x;
    if (i < e) atomicAdd(&g_deg[dst[i]], 1);
}
__global__ void k_scan(int n) {
    __shared__ int s[1024];
    int t = threadIdx.x;
    int chunk = (n + 1023) >> 10;
    int beg = t * chunk;
    int end = beg + chunk; if (end > n) end = n;
    int sum = 0;
    for (int i = beg; i < end; i++) sum += g_deg[i];
    s[t] = sum;
    __syncthreads();
    for (int off = 1; off < 1024; off <<= 1) {
        int v = 0;
        if (t >= off) v = s[t - off];
        __syncthreads();
        if (t >= off) s[t] += v;
        __syncthreads();
    }
    int prefix = (t == 0) ? 0 : s[t - 1];
    for (int i = beg; i < end; i++) {
        g_rowptr[i] = prefix;
        prefix += g_deg[i];
        g_cur[i] = 0;
    }
    if (t == 1023) g_rowptr[n] = s[1023];
}
__global__ void k_scatter(const int* __restrict__ src, const int* __restrict__ dst, int e) {
    int i = blockIdx.x * blockDim.x + threadIdx.x;
    if (i >= e) return;
    int d = dst[i];
    int pos = g_rowptr[d] + atomicAdd(&g_cur[d], 1);
    g_col[pos] = src[i];
}

// ---------------- GEMM: C[n x 64] = A[n x K] @ B[K x 64] ----------------
// 128x64 tile, 256 threads, 8 rows x 4 cols per thread.
// A stored DUPLICATED in smem (As2[m][2k]=As2[m][2k+1]=a): LDS.64 yields packed (a,a)
// directly; B pairs loaded as LDS.64 — inner loop has ZERO pack movs:
// per k: 4 LDS.64 + 2 LDS.64 + 16 fma2 = 22 instrs (was 35).
#define ASTR2 136   // floats per A row (2*64 duplicated + 8 pad)
#define BSTR  68
#define SMEM_GEMM ((128 * ASTR2 + 64 * BSTR) * 4)
__global__ void __launch_bounds__(256) k_gemm128(
        const float* __restrict__ A, const float* __restrict__ B,
        const float* __restrict__ bias,
        const float* __restrict__ a_s, const float* __restrict__ a_d,
        float* __restrict__ C, int n, int K) {
    extern __shared__ float sm[];
    float* As = sm;                       // [128][ASTR2]
    float* Bs = sm + 128 * ASTR2;         // [64][BSTR]
    const int tid = threadIdx.x;
    const int tx = tid & 15;
    const int ty = tid >> 4;
    const int row0 = blockIdx.x * 128;

    ull acc[8][2];
#pragma unroll
    for (int i = 0; i < 8; i++) { acc[i][0] = 0ull; acc[i][1] = 0ull; }

    for (int k0 = 0; k0 < K; k0 += 64) {
        // A tile: 128 rows x 64 k, duplicated: As[m][2k..2k+1] = a
#pragma unroll
        for (int l = 0; l < 8; l++) {
            int idx = tid + l * 256;
            int m = idx >> 4;
            int kq = idx & 15;
            int grow = row0 + m;
            float4 v = make_float4(0.f, 0.f, 0.f, 0.f);
            if (grow < n)
                v = *reinterpret_cast<const float4*>(A + (size_t)grow * K + k0 + kq * 4);
            float* p = &As[m * ASTR2 + kq * 8];
            *reinterpret_cast<float4*>(p)     = make_float4(v.x, v.x, v.y, v.y);
            *reinterpret_cast<float4*>(p + 4) = make_float4(v.z, v.z, v.w, v.w);
        }
        // B tile
#pragma unroll
        for (int l = 0; l < 4; l++) {
            int idx = tid + l * 256;
            int k = idx >> 4;
            int jq = idx & 15;
            float4 v = *reinterpret_cast<const float4*>(B + (size_t)(k0 + k) * 64 + jq * 4);
            *reinterpret_cast<float4*>(&Bs[k * BSTR + jq * 4]) = v;
        }
        __syncthreads();
#pragma unroll 4
        for (int k = 0; k < 64; k++) {
            ull b01 = *reinterpret_cast<const ull*>(&Bs[k * BSTR + tx * 4]);
            ull b23 = *reinterpret_cast<const ull*>(&Bs[k * BSTR + tx * 4 + 2]);
#pragma unroll
            for (int i = 0; i < 8; i++) {
                ull aa = *reinterpret_cast<const ull*>(&As[(ty * 8 + i) * ASTR2 + 2 * k]);
                fma2(acc[i][0], aa, b01);
                fma2(acc[i][1], aa, b23);
            }
        }
        __syncthreads();
    }

    float4 asv = make_float4(0.f, 0.f, 0.f, 0.f), adv = asv, bv = asv;
    if (a_s) {
        asv = *reinterpret_cast<const float4*>(a_s + tx * 4);
        adv = *reinterpret_cast<const float4*>(a_d + tx * 4);
    }
    if (bias) bv = *reinterpret_cast<const float4*>(bias + tx * 4);

#pragma unroll
    for (int i = 0; i < 8; i++) {
        int grow = row0 + ty * 8 + i;
        float2 p0 = unpack2(acc[i][0]);
        float2 p1 = unpack2(acc[i][1]);
        float c0 = p0.x, c1 = p0.y, c2 = p1.x, c3 = p1.y;
        if (bias) { c0 += bv.x; c1 += bv.y; c2 += bv.z; c3 += bv.w; }
        if (grow < n)
            *reinterpret_cast<float4*>(C + (size_t)grow * 64 + tx * 4) = make_float4(c0, c1, c2, c3);
        if (a_s) {
            float es = c0 * asv.x + c1 * asv.y + c2 * asv.z + c3 * asv.w;
            float ed = c0 * adv.x + c1 * adv.y + c2 * adv.z + c3 * adv.w;
#pragma unroll
            for (int o = 8; o; o >>= 1) {
                es += __shfl_xor_sync(0xffffffffu, es, o);
                ed += __shfl_xor_sync(0xffffffffu, ed, o);
            }
            if (tx == 0 && grow < n) { g_es[grow] = es; g_ed[grow] = ed; }
        }
    }
}

// ---------------- aggregation: HALF-WARP per dst node ----------------
// 16 lanes own the 64 features as float4 -> one LDG.128 per edge per half-warp.
// A warp serves 2 nodes: per-edge instruction count halves, independent load
// streams double. Uniform (col, es) loads serve both halves in one instr.
// mode 0: relu(out + bias); mode 1: (out + bias) then row L2-normalize
__global__ void __launch_bounds__(256) k_agg(const float* __restrict__ bias,
                                             float* __restrict__ out, int n, int mode) {
    int warp_id = (blockIdx.x * blockDim.x + threadIdx.x) >> 5;
    int lane = threadIdx.x & 31;
    int half = lane >> 4;
    int hl = lane & 15;
    int w = warp_id * 2 + half;
    if (w >= n) return;

    int beg = g_rowptr[w], end = g_rowptr[w + 1];
    int cnt = end - beg;
    float edd = g_ed[w];

    float ex_self = __expf(leaky(g_es[w] + edd));
    float4 hv = *reinterpret_cast<const float4*>(g_lin + (size_t)w * 64 + hl * 4);
    ull ex2 = pack2(ex_self, ex_self);
    ull acc01 = 0ull, acc23 = 0ull;
    fma2(acc01, ex2, pack2(hv.x, hv.y));
    fma2(acc23, ex2, pack2(hv.z, hv.w));
    float den = ex_self;

    int j = 0;
    for (; j + 4 <= cnt; j += 4) {
        int k = beg + j;
        int s0 = g_col[k];
        int s1 = g_col[k + 1];
        int s2 = g_col[k + 2];
        int s3 = g_col[k + 3];
        float q0 = g_es[s0], q1 = g_es[s1], q2 = g_es[s2], q3 = g_es[s3];
        float4 v0 = *reinterpret_cast<const float4*>(g_lin + (size_t)s0 * 64 + hl * 4);
        float4 v1 = *reinterpret_cast<const float4*>(g_lin + (size_t)s1 * 64 + hl * 4);
        float4 v2 = *reinterpret_cast<const float4*>(g_lin + (size_t)s2 * 64 + hl * 4);
        float4 v3 = *reinterpret_cast<const float4*>(g_lin + (size_t)s3 * 64 + hl * 4);
        float e0 = __expf(leaky(q0 + edd));
        float e1 = __expf(leaky(q1 + edd));
        float e2 = __expf(leaky(q2 + edd));
        float e3 = __expf(leaky(q3 + edd));
        den += e0 + e1 + e2 + e3;
        ull p0 = pack2(e0, e0), p1 = pack2(e1, e1), p2 = pack2(e2, e2), p3 = pack2(e3, e3);
        fma2(acc01, p0, pack2(v0.x, v0.y)); fma2(acc23, p0, pack2(v0.z, v0.w));
        fma2(acc01, p1, pack2(v1.x, v1.y)); fma2(acc23, p1, pack2(v1.z, v1.w));
        fma2(acc01, p2, pack2(v2.x, v2.y)); fma2(acc23, p2, pack2(v2.z, v2.w));
        fma2(acc01, p3, pack2(v3.x, v3.y)); fma2(acc23, p3, pack2(v3.z, v3.w));
    }
    for (; j < cnt; j++) {
        int s = g_col[beg + j];
        float ex = __expf(leaky(g_es[s] + edd));
        float4 v = *reinterpret_cast<const float4*>(g_lin + (size_t)s * 64 + hl * 4);
        den += ex;
        ull p = pack2(ex, ex);
        fma2(acc01, p, pack2(v.x, v.y));
        fma2(acc23, p, pack2(v.z, v.w));
    }

    float inv = 1.f / (den + 1e-16f);
    float4 bvec = *reinterpret_cast<const float4*>(bias + hl * 4);
    float2 a01 = unpack2(acc01);
    float2 a23 = unpack2(acc23);
    float o0 = a01.x * inv + bvec.x;
    float o1 = a01.y * inv + bvec.y;
    float o2 = a23.x * inv + bvec.z;
    float o3 = a23.y * inv + bvec.w;
    if (mode == 0) {
        o0 = fmaxf(o0, 0.f); o1 = fmaxf(o1, 0.f);
        o2 = fmaxf(o2, 0.f); o3 = fmaxf(o3, 0.f);
    } else {
        float ss = o0 * o0 + o1 * o1 + o2 * o2 + o3 * o3;
#pragma unroll
        for (int o = 8; o; o >>= 1) ss += __shfl_xor_sync(0xffffffffu, ss, o);  // within half
        float nrm = fmaxf(sqrtf(ss), 1e-12f);
        o0 /= nrm; o1 /= nrm; o2 /= nrm; o3 /= nrm;
    }
    *reinterpret_cast<float4*>(out + (size_t)w * 64 + hl * 4) = make_float4(o0, o1, o2, o3);
}

// ---------------- launch ----------------
extern "C" void kernel_launch(void* const* d_in, const int* in_sizes, int n_in,
                              void* d_out, int out_size) {
    const float* x     = (const float*)d_in[0];
    const int*   src   = (const int*)d_in[1];
    const int*   dst   = (const int*)d_in[2];
    const float* lin_w = (const float*)d_in[3];
    const float* lin_b = (const float*)d_in[4];
    const float* W[3]  = { (const float*)d_in[5],  (const float*)d_in[9],  (const float*)d_in[13] };
    const float* AS[3] = { (const float*)d_in[6],  (const float*)d_in[10], (const float*)d_in[14] };
    const float* AD[3] = { (const float*)d_in[7],  (const float*)d_in[11], (const float*)d_in[15] };
    const float* BI[3] = { (const float*)d_in[8],  (const float*)d_in[12], (const float*)d_in[16] };

    const int n = in_sizes[0] / 256;   // 100000
    const int e = in_sizes[1];         // 1280000

    float *hA, *hB, *lin;
    int *degp;
    cudaGetSymbolAddress((void**)&hA,   g_hA);
    cudaGetSymbolAddress((void**)&hB,   g_hB);
    cudaGetSymbolAddress((void**)&lin,  g_lin);
    cudaGetSymbolAddress((void**)&degp, g_deg);

    static int smem_set = 0;
    if (!smem_set) {
        cudaFuncSetAttribute(k_gemm128, cudaFuncAttributeMaxDynamicSharedMemorySize, SMEM_GEMM);
        smem_set = 1;
    }

    const int TB = 256;
    dim3 gE((e + TB - 1) / TB);
    dim3 gG((n + 127) / 128);
    dim3 gW(((n + 1) / 2 + 7) / 8);    // half-warp per node, 8 warps/block

    // CSR by dst (graph fixed across all 3 layers)
    cudaMemsetAsync(degp, 0, (size_t)n * sizeof(int));
    k_hist<<<gE, TB>>>(dst, e);
    k_scan<<<1, 1024>>>(n);
    k_scatter<<<gE, TB>>>(src, dst, e);

    // feature_pre: h0 = x @ lin_w + lin_b
    k_gemm128<<<gG, TB, SMEM_GEMM>>>(x, lin_w, lin_b, nullptr, nullptr, hA, n, 256);

    // Layer 1
    k_gemm128<<<gG, TB, SMEM_GEMM>>>(hA, W[0], nullptr, AS[0], AD[0], lin, n, 64);
    k_agg<<<gW, TB>>>(BI[0], hB, n, 0);

    // Layer 2
    k_gemm128<<<gG, TB, SMEM_GEMM>>>(hB, W[1], nullptr, AS[1], AD[1], lin, n, 64);
    k_agg<<<gW, TB>>>(BI[1], hA, n, 0);

    // Layer 3 (+ row L2 normalize) -> d_out
    k_gemm128<<<gG, TB, SMEM_GEMM>>>(hA, W[2], nullptr, AS[2], AD[2], lin, n, 64);
    k_agg<<<gW, TB>>>(BI[2], (float*)d_out, n, 1);
}

// round 13
// speedup vs baseline: 1.1149x; 1.1149x over previous
#include <cuda_runtime.h>
#include <math.h>

// N=100000, E=1280000, IN_D=256, FEAT=HID=OUT=64
#define NMAX 100000
#define EMAX 1280000
#define NEG_SLOPE 0.2f

// ---------------- scratch ----------------
__device__ float g_hA[NMAX * 64];
__device__ float g_hB[NMAX * 64];
__device__ float g_lin[NMAX * 64];
__device__ float g_es[NMAX];
__device__ float g_ed[NMAX];
__device__ int   g_deg[NMAX];
__device__ int   g_cur[NMAX];
__device__ int   g_rowptr[NMAX + 1];
__device__ int   g_col[EMAX];

__device__ __forceinline__ float leaky(float x) { return x > 0.f ? x : NEG_SLOPE * x; }

typedef unsigned long long ull;
__device__ __forceinline__ void fma2(ull& d, ull a, ull b) {
    asm("fma.rn.f32x2 %0, %1, %2, %0;" : "+l"(d) : "l"(a), "l"(b));
}
__device__ __forceinline__ ull pack2(float lo, float hi) {
    ull r;
    asm("mov.b64 %0, {%1, %2};" : "=l"(r) : "f"(lo), "f"(hi));
    return r;
}
__device__ __forceinline__ float2 unpack2(ull v) {
    float2 f;
    asm("mov.b64 {%0, %1}, %2;" : "=f"(f.x), "=f"(f.y) : "l"(v));
    return f;
}

// ---------------- CSR build ----------------
__global__ void k_hist(const int* __restrict__ dst, int e) {
    int i = blockIdx.x * blockDim.x + threadIdx.x;
    if (i < e) atomicAdd(&g_deg[dst[i]], 1);
}
__global__ void k_scan(int n) {
    __shared__ int s[1024];
    int t = threadIdx.x;
    int chunk = (n + 1023) >> 10;
    int beg = t * chunk;
    int end = beg + chunk; if (end > n) end = n;
    int sum = 0;
    for (int i = beg; i < end; i++) sum += g_deg[i];
    s[t] = sum;
    __syncthreads();
    for (int off = 1; off < 1024; off <<= 1) {
        int v = 0;
        if (t >= off) v = s[t - off];
        __syncthreads();
        if (t >= off) s[t] += v;
        __syncthreads();
    }
    int prefix = (t == 0) ? 0 : s[t - 1];
    for (int i = beg; i < end; i++) {
        g_rowptr[i] = prefix;
        prefix += g_deg[i];
        g_cur[i] = 0;
    }
    if (t == 1023) g_rowptr[n] = s[1023];
}
__global__ void k_scatter(const int* __restrict__ src, const int* __restrict__ dst, int e) {
    int i = blockIdx.x * blockDim.x + threadIdx.x;
    if (i >= e) return;
    int d = dst[i];
    int pos = g_rowptr[d] + atomicAdd(&g_cur[d], 1);
    g_col[pos] = src[i];
}

// ---------------- GEMM: C[n x 64] = A[n x K] @ B[K x 64] ----------------
// EXACT 479.5us configuration: 128x64 tile, 256 threads, 8x4 per thread,
// f32x2 FMAs with in-loop packs, static smem, no min-blocks clamp.
#define ASTR 68
#define BSTR 68
__global__ void __launch_bounds__(256) k_gemm128(
        const float* __restrict__ A, const float* __restrict__ B,
        const float* __restrict__ bias,
        const float* __restrict__ a_s, const float* __restrict__ a_d,
        float* __restrict__ C, int n, int K) {
    __shared__ float As[128 * ASTR];   // As[m][k]
    __shared__ float Bs[64 * BSTR];    // Bs[k][j]
    const int tid = threadIdx.x;
    const int tx = tid & 15;
    const int ty = tid >> 4;
    const int row0 = blockIdx.x * 128;

    ull acc[8][2];
#pragma unroll
    for (int i = 0; i < 8; i++) { acc[i][0] = 0ull; acc[i][1] = 0ull; }

    for (int k0 = 0; k0 < K; k0 += 64) {
#pragma unroll
        for (int l = 0; l < 8; l++) {
            int idx = tid + l * 256;
            int m = idx >> 4;
            int kq = idx & 15;
            int grow = row0 + m;
            float4 v = make_float4(0.f, 0.f, 0.f, 0.f);
            if (grow < n)
                v = *reinterpret_cast<const float4*>(A + (size_t)grow * K + k0 + kq * 4);
            *reinterpret_cast<float4*>(&As[m * ASTR + kq * 4]) = v;
        }
#pragma unroll
        for (int l = 0; l < 4; l++) {
            int idx = tid + l * 256;
            int k = idx >> 4;
            int jq = idx & 15;
            float4 v = *reinterpret_cast<const float4*>(B + (size_t)(k0 + k) * 64 + jq * 4);
            *reinterpret_cast<float4*>(&Bs[k * BSTR + jq * 4]) = v;
        }
        __syncthreads();
#pragma unroll 4
        for (int k = 0; k < 64; k++) {
            float4 b = *reinterpret_cast<const float4*>(&Bs[k * BSTR + tx * 4]);
            ull b01 = pack2(b.x, b.y);
            ull b23 = pack2(b.z, b.w);
#pragma unroll
            for (int i = 0; i < 8; i++) {
                float a = As[(ty * 8 + i) * ASTR + k];
                ull aa = pack2(a, a);
                fma2(acc[i][0], aa, b01);
                fma2(acc[i][1], aa, b23);
            }
        }
        __syncthreads();
    }

    float4 asv = make_float4(0.f, 0.f, 0.f, 0.f), adv = asv, bv = asv;
    if (a_s) {
        asv = *reinterpret_cast<const float4*>(a_s + tx * 4);
        adv = *reinterpret_cast<const float4*>(a_d + tx * 4);
    }
    if (bias) bv = *reinterpret_cast<const float4*>(bias + tx * 4);

#pragma unroll
    for (int i = 0; i < 8; i++) {
        int grow = row0 + ty * 8 + i;
        float2 p0 = unpack2(acc[i][0]);
        float2 p1 = unpack2(acc[i][1]);
        float c0 = p0.x, c1 = p0.y, c2 = p1.x, c3 = p1.y;
        if (bias) { c0 += bv.x; c1 += bv.y; c2 += bv.z; c3 += bv.w; }
        if (grow < n)
            *reinterpret_cast<float4*>(C + (size_t)grow * 64 + tx * 4) = make_float4(c0, c1, c2, c3);
        if (a_s) {
            float es = c0 * asv.x + c1 * asv.y + c2 * asv.z + c3 * asv.w;
            float ed = c0 * adv.x + c1 * adv.y + c2 * adv.z + c3 * adv.w;
#pragma unroll
            for (int o = 8; o; o >>= 1) {
                es += __shfl_xor_sync(0xffffffffu, es, o);
                ed += __shfl_xor_sync(0xffffffffu, ed, o);
            }
            if (tx == 0 && grow < n) { g_es[grow] = es; g_ed[grow] = ed; }
        }
    }
}

// ---------------- aggregation: warp per dst, uniform edge loop, 8x unroll ----------------
// All lanes redundantly load (s, es[s]) at uniform addresses (one L2 request each)
// and compute ex — no shuffles, no reductions (den lane-uniform). Lane owns feature
// pair (2*lane, 2*lane+1): one LDG.64 + one fma.f32x2 per edge. 8x unroll for MLP.
__global__ void __launch_bounds__(256) k_agg(const float* __restrict__ bias,
                                             float* __restrict__ out, int n, int mode) {
    int w = (blockIdx.x * blockDim.x + threadIdx.x) >> 5;
    if (w >= n) return;
    int lane = threadIdx.x & 31;
    int beg = g_rowptr[w], end = g_rowptr[w + 1];
    float edd = g_ed[w];

    float ex_self = __expf(leaky(g_es[w] + edd));
    float2 hv = *reinterpret_cast<const float2*>(g_lin + (size_t)w * 64 + 2 * lane);
    ull acc = 0ull;
    fma2(acc, pack2(ex_self, ex_self), pack2(hv.x, hv.y));
    float den = ex_self;

    int k = beg;
    for (; k + 8 <= end; k += 8) {
        int s0 = g_col[k],     s1 = g_col[k + 1], s2 = g_col[k + 2], s3 = g_col[k + 3];
        int s4 = g_col[k + 4], s5 = g_col[k + 5], s6 = g_col[k + 6], s7 = g_col[k + 7];
        float q0 = g_es[s0], q1 = g_es[s1], q2 = g_es[s2], q3 = g_es[s3];
        float q4 = g_es[s4], q5 = g_es[s5], q6 = g_es[s6], q7 = g_es[s7];
        float2 v0 = *reinterpret_cast<const float2*>(g_lin + (size_t)s0 * 64 + 2 * lane);
        float2 v1 = *reinterpret_cast<const float2*>(g_lin + (size_t)s1 * 64 + 2 * lane);
        float2 v2 = *reinterpret_cast<const float2*>(g_lin + (size_t)s2 * 64 + 2 * lane);
        float2 v3 = *reinterpret_cast<const float2*>(g_lin + (size_t)s3 * 64 + 2 * lane);
        float2 v4 = *reinterpret_cast<const float2*>(g_lin + (size_t)s4 * 64 + 2 * lane);
        float2 v5 = *reinterpret_cast<const float2*>(g_lin + (size_t)s5 * 64 + 2 * lane);
        float2 v6 = *reinterpret_cast<const float2*>(g_lin + (size_t)s6 * 64 + 2 * lane);
        float2 v7 = *reinterpret_cast<const float2*>(g_lin + (size_t)s7 * 64 + 2 * lane);
        float e0 = __expf(leaky(q0 + edd)), e1 = __expf(leaky(q1 + edd));
        float e2 = __expf(leaky(q2 + edd)), e3 = __expf(leaky(q3 + edd));
        float e4 = __expf(leaky(q4 + edd)), e5 = __expf(leaky(q5 + edd));
        float e6 = __expf(leaky(q6 + edd)), e7 = __expf(leaky(q7 + edd));
        den += e0 + e1 + e2 + e3 + e4 + e5 + e6 + e7;
        fma2(acc, pack2(e0, e0), pack2(v0.x, v0.y));
        fma2(acc, pack2(e1, e1), pack2(v1.x, v1.y));
        fma2(acc, pack2(e2, e2), pack2(v2.x, v2.y));
        fma2(acc, pack2(e3, e3), pack2(v3.x, v3.y));
        fma2(acc, pack2(e4, e4), pack2(v4.x, v4.y));
        fma2(acc, pack2(e5, e5), pack2(v5.x, v5.y));
        fma2(acc, pack2(e6, e6), pack2(v6.x, v6.y));
        fma2(acc, pack2(e7, e7), pack2(v7.x, v7.y));
    }
    for (; k < end; k++) {
        int s = g_col[k];
        float ex = __expf(leaky(g_es[s] + edd));
        float2 v = *reinterpret_cast<const float2*>(g_lin + (size_t)s * 64 + 2 * lane);
        den += ex;
        fma2(acc, pack2(ex, ex), pack2(v.x, v.y));
    }

    float inv = 1.f / (den + 1e-16f);
    float2 bvec = *reinterpret_cast<const float2*>(bias + 2 * lane);
    float2 av = unpack2(acc);
    float o0 = av.x * inv + bvec.x;
    float o1 = av.y * inv + bvec.y;
    if (mode == 0) {
        o0 = fmaxf(o0, 0.f);
        o1 = fmaxf(o1, 0.f);
    } else {
        float ss = o0 * o0 + o1 * o1;
#pragma unroll
        for (int o = 16; o; o >>= 1) ss += __shfl_xor_sync(0xffffffffu, ss, o);
        float nrm = fmaxf(sqrtf(ss), 1e-12f);
        o0 /= nrm; o1 /= nrm;
    }
    *reinterpret_cast<float2*>(out + (size_t)w * 64 + 2 * lane) = make_float2(o0, o1);
}

// ---------------- launch ----------------
extern "C" void kernel_launch(void* const* d_in, const int* in_sizes, int n_in,
                              void* d_out, int out_size) {
    const float* x     = (const float*)d_in[0];
    const int*   src   = (const int*)d_in[1];
    const int*   dst   = (const int*)d_in[2];
    const float* lin_w = (const float*)d_in[3];
    const float* lin_b = (const float*)d_in[4];
    const float* W[3]  = { (const float*)d_in[5],  (const float*)d_in[9],  (const float*)d_in[13] };
    const float* AS[3] = { (const float*)d_in[6],  (const float*)d_in[10], (const float*)d_in[14] };
    const float* AD[3] = { (const float*)d_in[7],  (const float*)d_in[11], (const float*)d_in[15] };
    const float* BI[3] = { (const float*)d_in[8],  (const float*)d_in[12], (const float*)d_in[16] };

    const int n = in_sizes[0] / 256;   // 100000
    const int e = in_sizes[1];         // 1280000

    float *hA, *hB, *lin;
    int *degp;
    cudaGetSymbolAddress((void**)&hA,   g_hA);
    cudaGetSymbolAddress((void**)&hB,   g_hB);
    cudaGetSymbolAddress((void**)&lin,  g_lin);
    cudaGetSymbolAddress((void**)&degp, g_deg);

    // Side stream + events for CSR/GEMM overlap (created once; capture-safe fork/join)
    static cudaStream_t s2 = nullptr;
    static cudaEvent_t evFork = nullptr, evJoin = nullptr;
    if (!s2) {
        cudaStreamCreate(&s2);
        cudaEventCreateWithFlags(&evFork, cudaEventDisableTiming);
        cudaEventCreateWithFlags(&evJoin, cudaEventDisableTiming);
    }

    const int TB = 256;
    dim3 gE((e + TB - 1) / TB);
    dim3 gG((n + 127) / 128);
    dim3 gW((n + 7) / 8);

    // Fork: CSR build on s2, concurrent with pre-GEMM + gemm1 on main stream.
    cudaEventRecord(evFork, 0);
    cudaStreamWaitEvent(s2, evFork, 0);

    cudaMemsetAsync(degp, 0, (size_t)n * sizeof(int), s2);
    k_hist<<<gE, TB, 0, s2>>>(dst, e);
    k_scan<<<1, 1024, 0, s2>>>(n);
    k_scatter<<<gE, TB, 0, s2>>>(src, dst, e);
    cudaEventRecord(evJoin, s2);

    // feature_pre: h0 = x @ lin_w + lin_b   (independent of CSR)
    k_gemm128<<<gG, TB>>>(x, lin_w, lin_b, nullptr, nullptr, hA, n, 256);

    // Layer 1 gemm (+fused es/ed) — also independent of CSR
    k_gemm128<<<gG, TB>>>(hA, W[0], nullptr, AS[0], AD[0], lin, n, 64);

    // Join: aggregation needs the CSR
    cudaStreamWaitEvent(0, evJoin, 0);
    k_agg<<<gW, TB>>>(BI[0], hB, n, 0);

    // Layer 2
    k_gemm128<<<gG, TB>>>(hB, W[1], nullptr, AS[1], AD[1], lin, n, 64);
    k_agg<<<gW, TB>>>(BI[1], hA, n, 0);

    // Layer 3 (+ row L2 normalize) -> d_out
    k_gemm128<<<gG, TB>>>(hA, W[2], nullptr, AS[2], AD[2], lin, n, 64);
    k_agg<<<gW, TB>>>(BI[2], (float*)d_out, n, 1);
}

// round 14
// speedup vs baseline: 1.1764x; 1.0552x over previous
#include <cuda_runtime.h>
#include <math.h>

// N=100000, E=1280000, IN_D=256, FEAT=HID=OUT=64
#define NMAX 100000
#define EMAX 1280000
#define NEG_SLOPE 0.2f

// ---------------- scratch ----------------
__device__ float g_hA[NMAX * 64];
__device__ float g_hB[NMAX * 64];
__device__ float g_lin[NMAX * 64];
__device__ float g_es[NMAX];
__device__ float g_ed[NMAX];
__device__ int   g_deg[NMAX];
__device__ int   g_cur[NMAX];
__device__ int   g_rowptr[NMAX + 1];
__device__ int   g_col[EMAX];

__device__ __forceinline__ float leaky(float x) { return x > 0.f ? x : NEG_SLOPE * x; }

typedef unsigned long long ull;
__device__ __forceinline__ void fma2(ull& d, ull a, ull b) {
    asm("fma.rn.f32x2 %0, %1, %2, %0;" : "+l"(d) : "l"(a), "l"(b));
}
__device__ __forceinline__ ull pack2(float lo, float hi) {
    ull r;
    asm("mov.b64 %0, {%1, %2};" : "=l"(r) : "f"(lo), "f"(hi));
    return r;
}
__device__ __forceinline__ float2 unpack2(ull v) {
    float2 f;
    asm("mov.b64 {%0, %1}, %2;" : "=f"(f.x), "=f"(f.y) : "l"(v));
    return f;
}

// TF32 helpers
__device__ __forceinline__ unsigned to_tf32(float x) {
    unsigned r;
    asm("cvt.rna.tf32.f32 %0, %1;" : "=r"(r) : "f"(x));
    return r;
}
__device__ __forceinline__ void mma_tf32(float& c0, float& c1, float& c2, float& c3,
                                         unsigned a0, unsigned a1, unsigned a2, unsigned a3,
                                         unsigned b0, unsigned b1) {
    asm("mma.sync.aligned.m16n8k8.row.col.f32.tf32.tf32.f32 "
        "{%0,%1,%2,%3}, {%4,%5,%6,%7}, {%8,%9}, {%0,%1,%2,%3};"
        : "+f"(c0), "+f"(c1), "+f"(c2), "+f"(c3)
        : "r"(a0), "r"(a1), "r"(a2), "r"(a3), "r"(b0), "r"(b1));
}

// ---------------- CSR build ----------------
__global__ void k_hist(const int* __restrict__ dst, int e) {
    int i = blockIdx.x * blockDim.x + threadIdx.x;
    if (i < e) atomicAdd(&g_deg[dst[i]], 1);
}
__global__ void k_scan(int n) {
    __shared__ int s[1024];
    int t = threadIdx.x;
    int chunk = (n + 1023) >> 10;
    int beg = t * chunk;
    int end = beg + chunk; if (end > n) end = n;
    int sum = 0;
    for (int i = beg; i < end; i++) sum += g_deg[i];
    s[t] = sum;
    __syncthreads();
    for (int off = 1; off < 1024; off <<= 1) {
        int v = 0;
        if (t >= off) v = s[t - off];
        __syncthreads();
        if (t >= off) s[t] += v;
        __syncthreads();
    }
    int prefix = (t == 0) ? 0 : s[t - 1];
    for (int i = beg; i < end; i++) {
        g_rowptr[i] = prefix;
        prefix += g_deg[i];
        g_cur[i] = 0;
    }
    if (t == 1023) g_rowptr[n] = s[1023];
}
__global__ void k_scatter(const int* __restrict__ src, const int* __restrict__ dst, int e) {
    int i = blockIdx.x * blockDim.x + threadIdx.x;
    if (i >= e) return;
    int d = dst[i];
    int pos = g_rowptr[d] + atomicAdd(&g_cur[d], 1);
    g_col[pos] = src[i];
}

// ---------------- TF32 tensor-core GEMM: C[n x 64] = A[n x K] @ B[K x 64] ----------------
// 128x64 tile per block, 8 warps; warp w owns rows 16w..16w+15 (m16), loops 8 n-tiles (n8),
// K in 64-wide smem stages, 8 k-steps (k8) each. Operands converted to tf32 at staging.
// Fused epilogue: +bias, and es/ed row-dots (reduced across the 4-lane quad).
#define ASTR 68
#define BSTR 68
__global__ void __launch_bounds__(256) k_gemm_tc(
        const float* __restrict__ A, const float* __restrict__ B,
        const float* __restrict__ bias,
        const float* __restrict__ a_s, const float* __restrict__ a_d,
        float* __restrict__ C, int n, int K) {
    __shared__ unsigned As[128 * ASTR];  // tf32 bits, As[m][k]
    __shared__ unsigned Bs[64 * BSTR];   // tf32 bits, Bs[k][j]
    const int tid = threadIdx.x;
    const int warp = tid >> 5;
    const int lane = tid & 31;
    const int g = lane >> 2;       // groupID (row within m16 half)
    const int tig = lane & 3;      // thread-in-group
    const int row0 = blockIdx.x * 128;
    const int mrow = warp * 16;

    float c[8][4];
#pragma unroll
    for (int nt = 0; nt < 8; nt++)
#pragma unroll
        for (int i = 0; i < 4; i++) c[nt][i] = 0.f;

    for (int k0 = 0; k0 < K; k0 += 64) {
        // stage A (128 x 64), converting to tf32
#pragma unroll
        for (int l = 0; l < 8; l++) {
            int idx = tid + l * 256;
            int m = idx >> 4;
            int kq = idx & 15;
            int grow = row0 + m;
            float4 v = make_float4(0.f, 0.f, 0.f, 0.f);
            if (grow < n)
                v = *reinterpret_cast<const float4*>(A + (size_t)grow * K + k0 + kq * 4);
            uint4 u = make_uint4(to_tf32(v.x), to_tf32(v.y), to_tf32(v.z), to_tf32(v.w));
            *reinterpret_cast<uint4*>(&As[m * ASTR + kq * 4]) = u;
        }
        // stage B (64 x 64)
#pragma unroll
        for (int l = 0; l < 4; l++) {
            int idx = tid + l * 256;
            int k = idx >> 4;
            int jq = idx & 15;
            float4 v = *reinterpret_cast<const float4*>(B + (size_t)(k0 + k) * 64 + jq * 4);
            uint4 u = make_uint4(to_tf32(v.x), to_tf32(v.y), to_tf32(v.z), to_tf32(v.w));
            *reinterpret_cast<uint4*>(&Bs[k * BSTR + jq * 4]) = u;
        }
        __syncthreads();

        // A fragments for all 8 k-steps (reused across all 8 n-tiles)
        unsigned a[8][4];
#pragma unroll
        for (int ks = 0; ks < 8; ks++) {
            int kk = ks * 8;
            a[ks][0] = As[(mrow + g)     * ASTR + kk + tig];
            a[ks][1] = As[(mrow + g + 8) * ASTR + kk + tig];
            a[ks][2] = As[(mrow + g)     * ASTR + kk + tig + 4];
            a[ks][3] = As[(mrow + g + 8) * ASTR + kk + tig + 4];
        }
#pragma unroll
        for (int nt = 0; nt < 8; nt++) {
#pragma unroll
            for (int ks = 0; ks < 8; ks++) {
                unsigned b0 = Bs[(ks * 8 + tig)     * BSTR + nt * 8 + g];
                unsigned b1 = Bs[(ks * 8 + tig + 4) * BSTR + nt * 8 + g];
                mma_tf32(c[nt][0], c[nt][1], c[nt][2], c[nt][3],
                         a[ks][0], a[ks][1], a[ks][2], a[ks][3], b0, b1);
            }
        }
        __syncthreads();
    }

    // epilogue: bias, store, fused es/ed row-dots
    int r0 = row0 + mrow + g;
    int r1 = r0 + 8;
    float es0 = 0.f, ed0 = 0.f, es1 = 0.f, ed1 = 0.f;
#pragma unroll
    for (int nt = 0; nt < 8; nt++) {
        int col = nt * 8 + 2 * tig;
        float b0v = 0.f, b1v = 0.f;
        if (bias) { b0v = bias[col]; b1v = bias[col + 1]; }
        float v0 = c[nt][0] + b0v, v1 = c[nt][1] + b1v;
        float v2 = c[nt][2] + b0v, v3 = c[nt][3] + b1v;
        if (r0 < n)
            *reinterpret_cast<float2*>(C + (size_t)r0 * 64 + col) = make_float2(v0, v1);
        if (r1 < n)
            *reinterpret_cast<float2*>(C + (size_t)r1 * 64 + col) = make_float2(v2, v3);
        if (a_s) {
            float s0 = a_s[col], s1 = a_s[col + 1];
            float d0 = a_d[col], d1 = a_d[col + 1];
            es0 += v0 * s0 + v1 * s1;  ed0 += v0 * d0 + v1 * d1;
            es1 += v2 * s0 + v3 * s1;  ed1 += v2 * d0 + v3 * d1;
        }
    }
    if (a_s) {
        // reduce across the 4-lane quad (lanes differing in bits 0,1 share g)
#pragma unroll
        for (int o = 1; o <= 2; o <<= 1) {
            es0 += __shfl_xor_sync(0xffffffffu, es0, o);
            ed0 += __shfl_xor_sync(0xffffffffu, ed0, o);
            es1 += __shfl_xor_sync(0xffffffffu, es1, o);
            ed1 += __shfl_xor_sync(0xffffffffu, ed1, o);
        }
        if (tig == 0) {
            if (r0 < n) { g_es[r0] = es0; g_ed[r0] = ed0; }
            if (r1 < n) { g_es[r1] = es1; g_ed[r1] = ed1; }
        }
    }
}

// ---------------- aggregation: warp per dst, uniform edge loop, 8x unroll ----------------
__global__ void __launch_bounds__(256) k_agg(const float* __restrict__ bias,
                                             float* __restrict__ out, int n, int mode) {
    int w = (blockIdx.x * blockDim.x + threadIdx.x) >> 5;
    if (w >= n) return;
    int lane = threadIdx.x & 31;
    int beg = g_rowptr[w], end = g_rowptr[w + 1];
    float edd = g_ed[w];

    float ex_self = __expf(leaky(g_es[w] + edd));
    float2 hv = *reinterpret_cast<const float2*>(g_lin + (size_t)w * 64 + 2 * lane);
    ull acc = 0ull;
    fma2(acc, pack2(ex_self, ex_self), pack2(hv.x, hv.y));
    float den = ex_self;

    int k = beg;
    for (; k + 8 <= end; k += 8) {
        int s0 = g_col[k],     s1 = g_col[k + 1], s2 = g_col[k + 2], s3 = g_col[k + 3];
        int s4 = g_col[k + 4], s5 = g_col[k + 5], s6 = g_col[k + 6], s7 = g_col[k + 7];
        float q0 = g_es[s0], q1 = g_es[s1], q2 = g_es[s2], q3 = g_es[s3];
        float q4 = g_es[s4], q5 = g_es[s5], q6 = g_es[s6], q7 = g_es[s7];
        float2 v0 = *reinterpret_cast<const float2*>(g_lin + (size_t)s0 * 64 + 2 * lane);
        float2 v1 = *reinterpret_cast<const float2*>(g_lin + (size_t)s1 * 64 + 2 * lane);
        float2 v2 = *reinterpret_cast<const float2*>(g_lin + (size_t)s2 * 64 + 2 * lane);
        float2 v3 = *reinterpret_cast<const float2*>(g_lin + (size_t)s3 * 64 + 2 * lane);
        float2 v4 = *reinterpret_cast<const float2*>(g_lin + (size_t)s4 * 64 + 2 * lane);
        float2 v5 = *reinterpret_cast<const float2*>(g_lin + (size_t)s5 * 64 + 2 * lane);
        float2 v6 = *reinterpret_cast<const float2*>(g_lin + (size_t)s6 * 64 + 2 * lane);
        float2 v7 = *reinterpret_cast<const float2*>(g_lin + (size_t)s7 * 64 + 2 * lane);
        float e0 = __expf(leaky(q0 + edd)), e1 = __expf(leaky(q1 + edd));
        float e2 = __expf(leaky(q2 + edd)), e3 = __expf(leaky(q3 + edd));
        float e4 = __expf(leaky(q4 + edd)), e5 = __expf(leaky(q5 + edd));
        float e6 = __expf(leaky(q6 + edd)), e7 = __expf(leaky(q7 + edd));
        den += e0 + e1 + e2 + e3 + e4 + e5 + e6 + e7;
        fma2(acc, pack2(e0, e0), pack2(v0.x, v0.y));
        fma2(acc, pack2(e1, e1), pack2(v1.x, v1.y));
        fma2(acc, pack2(e2, e2), pack2(v2.x, v2.y));
        fma2(acc, pack2(e3, e3), pack2(v3.x, v3.y));
        fma2(acc, pack2(e4, e4), pack2(v4.x, v4.y));
        fma2(acc, pack2(e5, e5), pack2(v5.x, v5.y));
        fma2(acc, pack2(e6, e6), pack2(v6.x, v6.y));
        fma2(acc, pack2(e7, e7), pack2(v7.x, v7.y));
    }
    for (; k < end; k++) {
        int s = g_col[k];
        float ex = __expf(leaky(g_es[s] + edd));
        float2 v = *reinterpret_cast<const float2*>(g_lin + (size_t)s * 64 + 2 * lane);
        den += ex;
        fma2(acc, pack2(ex, ex), pack2(v.x, v.y));
    }

    float inv = 1.f / (den + 1e-16f);
    float2 bvec = *reinterpret_cast<const float2*>(bias + 2 * lane);
    float2 av = unpack2(acc);
    float o0 = av.x * inv + bvec.x;
    float o1 = av.y * inv + bvec.y;
    if (mode == 0) {
        o0 = fmaxf(o0, 0.f);
        o1 = fmaxf(o1, 0.f);
    } else {
        float ss = o0 * o0 + o1 * o1;
#pragma unroll
        for (int o = 16; o; o >>= 1) ss += __shfl_xor_sync(0xffffffffu, ss, o);
        float nrm = fmaxf(sqrtf(ss), 1e-12f);
        o0 /= nrm; o1 /= nrm;
    }
    *reinterpret_cast<float2*>(out + (size_t)w * 64 + 2 * lane) = make_float2(o0, o1);
}

// ---------------- launch ----------------
extern "C" void kernel_launch(void* const* d_in, const int* in_sizes, int n_in,
                              void* d_out, int out_size) {
    const float* x     = (const float*)d_in[0];
    const int*   src   = (const int*)d_in[1];
    const int*   dst   = (const int*)d_in[2];
    const float* lin_w = (const float*)d_in[3];
    const float* lin_b = (const float*)d_in[4];
    const float* W[3]  = { (const float*)d_in[5],  (const float*)d_in[9],  (const float*)d_in[13] };
    const float* AS[3] = { (const float*)d_in[6],  (const float*)d_in[10], (const float*)d_in[14] };
    const float* AD[3] = { (const float*)d_in[7],  (const float*)d_in[11], (const float*)d_in[15] };
    const float* BI[3] = { (const float*)d_in[8],  (const float*)d_in[12], (const float*)d_in[16] };

    const int n = in_sizes[0] / 256;   // 100000
    const int e = in_sizes[1];         // 1280000

    float *hA, *hB, *lin;
    int *degp;
    cudaGetSymbolAddress((void**)&hA,   g_hA);
    cudaGetSymbolAddress((void**)&hB,   g_hB);
    cudaGetSymbolAddress((void**)&lin,  g_lin);
    cudaGetSymbolAddress((void**)&degp, g_deg);

    // Side stream + events for CSR/GEMM overlap (created once; capture-safe fork/join)
    static cudaStream_t s2 = nullptr;
    static cudaEvent_t evFork = nullptr, evJoin = nullptr;
    if (!s2) {
        cudaStreamCreate(&s2);
        cudaEventCreateWithFlags(&evFork, cudaEventDisableTiming);
        cudaEventCreateWithFlags(&evJoin, cudaEventDisableTiming);
    }

    const int TB = 256;
    dim3 gE((e + TB - 1) / TB);
    dim3 gG((n + 127) / 128);
    dim3 gW((n + 7) / 8);

    // Fork: CSR build on s2, concurrent with pre-GEMM + gemm1 on main stream.
    cudaEventRecord(evFork, 0);
    cudaStreamWaitEvent(s2, evFork, 0);

    cudaMemsetAsync(degp, 0, (size_t)n * sizeof(int), s2);
    k_hist<<<gE, TB, 0, s2>>>(dst, e);
    k_scan<<<1, 1024, 0, s2>>>(n);
    k_scatter<<<gE, TB, 0, s2>>>(src, dst, e);
    cudaEventRecord(evJoin, s2);

    // feature_pre: h0 = x @ lin_w + lin_b   (independent of CSR)
    k_gemm_tc<<<gG, TB>>>(x, lin_w, lin_b, nullptr, nullptr, hA, n, 256);

    // Layer 1 gemm (+fused es/ed) — also independent of CSR
    k_gemm_tc<<<gG, TB>>>(hA, W[0], nullptr, AS[0], AD[0], lin, n, 64);

    // Join: aggregation needs the CSR
    cudaStreamWaitEvent(0, evJoin, 0);
    k_agg<<<gW, TB>>>(BI[0], hB, n, 0);

    // Layer 2
    k_gemm_tc<<<gG, TB>>>(hB, W[1], nullptr, AS[1], AD[1], lin, n, 64);
    k_agg<<<gW, TB>>>(BI[1], hA, n, 0);

    // Layer 3 (+ row L2 normalize) -> d_out
    k_gemm_tc<<<gG, TB>>>(hA, W[2], nullptr, AS[2], AD[2], lin, n, 64);
    k_agg<<<gW, TB>>>(BI[2], (float*)d_out, n, 1);
}

// round 16
// speedup vs baseline: 1.4510x; 1.2335x over previous
#include <cuda_runtime.h>
#include <math.h>

// N=100000, E=1280000, IN_D=256, FEAT=HID=OUT=64
#define NMAX 100000
#define EMAX 1280000
#define NEG_SLOPE 0.2f

// ---------------- scratch ----------------
__device__ float g_hB[NMAX * 64];
__device__ float g_hA[NMAX * 64];
__device__ float g_lin[NMAX * 64];
__device__ float g_es[NMAX];
__device__ float g_ed[NMAX];
__device__ float g_ex[EMAX];          // per-CSR-slot exp(leaky(.))
__device__ int   g_deg[NMAX];
__device__ int   g_cur[NMAX];
__device__ int   g_rowptr[NMAX + 1];
__device__ int   g_col[EMAX];         // src per CSR slot
__device__ int   g_row[EMAX];         // dst per CSR slot
__device__ float g_Wp[256 * 64];      // lin_w @ W1
__device__ float g_bp[64];            // lin_b @ W1

__device__ __forceinline__ float leaky(float x) { return x > 0.f ? x : NEG_SLOPE * x; }

typedef unsigned long long ull;
__device__ __forceinline__ void fma2(ull& d, ull a, ull b) {
    asm("fma.rn.f32x2 %0, %1, %2, %0;" : "+l"(d) : "l"(a), "l"(b));
}
__device__ __forceinline__ ull pack2(float lo, float hi) {
    ull r;
    asm("mov.b64 %0, {%1, %2};" : "=l"(r) : "f"(lo), "f"(hi));
    return r;
}
__device__ __forceinline__ float2 unpack2(ull v) {
    float2 f;
    asm("mov.b64 {%0, %1}, %2;" : "=f"(f.x), "=f"(f.y) : "l"(v));
    return f;
}

// TF32 helpers
__device__ __forceinline__ unsigned to_tf32(float x) {
    unsigned r;
    asm("cvt.rna.tf32.f32 %0, %1;" : "=r"(r) : "f"(x));
    return r;
}
__device__ __forceinline__ void mma_tf32(float& c0, float& c1, float& c2, float& c3,
                                         unsigned a0, unsigned a1, unsigned a2, unsigned a3,
                                         unsigned b0, unsigned b1) {
    asm("mma.sync.aligned.m16n8k8.row.col.f32.tf32.tf32.f32 "
        "{%0,%1,%2,%3}, {%4,%5,%6,%7}, {%8,%9}, {%0,%1,%2,%3};"
        : "+f"(c0), "+f"(c1), "+f"(c2), "+f"(c3)
        : "r"(a0), "r"(a1), "r"(a2), "r"(a3), "r"(b0), "r"(b1));
}

// ---------------- CSR build ----------------
__global__ void k_hist(const int* __restrict__ dst, int e) {
    int i = blockIdx.x * blockDim.x + threadIdx.x;
    if (i < e) atomicAdd(&g_deg[dst[i]], 1);
}
__global__ void k_scan(int n) {
    __shared__ int s[1024];
    int t = threadIdx.x;
    int chunk = (n + 1023) >> 10;
    int beg = t * chunk;
    int end = beg + chunk; if (end > n) end = n;
    int sum = 0;
    for (int i = beg; i < end; i++) sum += g_deg[i];
    s[t] = sum;
    __syncthreads();
    for (int off = 1; off < 1024; off <<= 1) {
        int v = 0;
        if (t >= off) v = s[t - off];
        __syncthreads();
        if (t >= off) s[t] += v;
        __syncthreads();
    }
    int prefix = (t == 0) ? 0 : s[t - 1];
    for (int i = beg; i < end; i++) {
        g_rowptr[i] = prefix;
        prefix += g_deg[i];
        g_cur[i] = 0;
    }
    if (t == 1023) g_rowptr[n] = s[1023];
}
__global__ void k_scatter(const int* __restrict__ src, const int* __restrict__ dst, int e) {
    int i = blockIdx.x * blockDim.x + threadIdx.x;
    if (i >= e) return;
    int d = dst[i];
    int pos = g_rowptr[d] + atomicAdd(&g_cur[d], 1);
    g_col[pos] = src[i];
    g_row[pos] = d;
}

// ---------------- prep: Wp = lin_w @ W1, bp = lin_b @ W1 ----------------
__global__ void k_prep(const float* __restrict__ lin_w, const float* __restrict__ w1,
                       const float* __restrict__ lin_b) {
    int j = blockIdx.x * blockDim.x + threadIdx.x;  // 0..16383
    if (j >= 256 * 64) return;
    int col = j & 63, row = j >> 6;
    float s = 0.f;
#pragma unroll 8
    for (int k = 0; k < 64; k++) s += lin_w[row * 64 + k] * w1[k * 64 + col];
    g_Wp[row * 64 + col] = s;
    if (row == 0) {
        float b = 0.f;
#pragma unroll 8
        for (int k = 0; k < 64; k++) b += lin_b[k] * w1[k * 64 + col];
        g_bp[col] = b;
    }
}

// ---------------- TF32 tensor-core GEMM: C[n x 64] = A[n x K] @ B[K x 64] ----------------
#define ASTR 68
#define BSTR 68
__global__ void __launch_bounds__(256) k_gemm_tc(
        const float* __restrict__ A, const float* __restrict__ B,
        const float* __restrict__ bias,
        const float* __restrict__ a_s, const float* __restrict__ a_d,
        float* __restrict__ C, int n, int K) {
    __shared__ unsigned As[128 * ASTR];  // tf32 bits, As[m][k]
    __shared__ unsigned Bs[64 * BSTR];   // tf32 bits, Bs[k][j]
    const int tid = threadIdx.x;
    const int warp = tid >> 5;
    const int lane = tid & 31;
    const int g = lane >> 2;
    const int tig = lane & 3;
    const int row0 = blockIdx.x * 128;
    const int mrow = warp * 16;

    float c[8][4];
#pragma unroll
    for (int nt = 0; nt < 8; nt++)
#pragma unroll
        for (int i = 0; i < 4; i++) c[nt][i] = 0.f;

    for (int k0 = 0; k0 < K; k0 += 64) {
#pragma unroll
        for (int l = 0; l < 8; l++) {
            int idx = tid + l * 256;
            int m = idx >> 4;
            int kq = idx & 15;
            int grow = row0 + m;
            float4 v = make_float4(0.f, 0.f, 0.f, 0.f);
            if (grow < n)
                v = *reinterpret_cast<const float4*>(A + (size_t)grow * K + k0 + kq * 4);
            uint4 u = make_uint4(to_tf32(v.x), to_tf32(v.y), to_tf32(v.z), to_tf32(v.w));
            *reinterpret_cast<uint4*>(&As[m * ASTR + kq * 4]) = u;
        }
#pragma unroll
        for (int l = 0; l < 4; l++) {
            int idx = tid + l * 256;
            int k = idx >> 4;
            int jq = idx & 15;
            float4 v = *reinterpret_cast<const float4*>(B + (size_t)(k0 + k) * 64 + jq * 4);
            uint4 u = make_uint4(to_tf32(v.x), to_tf32(v.y), to_tf32(v.z), to_tf32(v.w));
            *reinterpret_cast<uint4*>(&Bs[k * BSTR + jq * 4]) = u;
        }
        __syncthreads();

        unsigned a[8][4];
#pragma unroll
        for (int ks = 0; ks < 8; ks++) {
            int kk = ks * 8;
            a[ks][0] = As[(mrow + g)     * ASTR + kk + tig];
            a[ks][1] = As[(mrow + g + 8) * ASTR + kk + tig];
            a[ks][2] = As[(mrow + g)     * ASTR + kk + tig + 4];
            a[ks][3] = As[(mrow + g + 8) * ASTR + kk + tig + 4];
        }
#pragma unroll
        for (int nt = 0; nt < 8; nt++) {
#pragma unroll
            for (int ks = 0; ks < 8; ks++) {
                unsigned b0 = Bs[(ks * 8 + tig)     * BSTR + nt * 8 + g];
                unsigned b1 = Bs[(ks * 8 + tig + 4) * BSTR + nt * 8 + g];
                mma_tf32(c[nt][0], c[nt][1], c[nt][2], c[nt][3],
                         a[ks][0], a[ks][1], a[ks][2], a[ks][3], b0, b1);
            }
        }
        __syncthreads();
    }

    int r0 = row0 + mrow + g;
    int r1 = r0 + 8;
    float es0 = 0.f, ed0 = 0.f, es1 = 0.f, ed1 = 0.f;
#pragma unroll
    for (int nt = 0; nt < 8; nt++) {
        int col = nt * 8 + 2 * tig;
        float b0v = 0.f, b1v = 0.f;
        if (bias) { b0v = bias[col]; b1v = bias[col + 1]; }
        float v0 = c[nt][0] + b0v, v1 = c[nt][1] + b1v;
        float v2 = c[nt][2] + b0v, v3 = c[nt][3] + b1v;
        if (r0 < n)
            *reinterpret_cast<float2*>(C + (size_t)r0 * 64 + col) = make_float2(v0, v1);
        if (r1 < n)
            *reinterpret_cast<float2*>(C + (size_t)r1 * 64 + col) = make_float2(v2, v3);
        if (a_s) {
            float s0 = a_s[col], s1 = a_s[col + 1];
            float d0 = a_d[col], d1 = a_d[col + 1];
            es0 += v0 * s0 + v1 * s1;  ed0 += v0 * d0 + v1 * d1;
            es1 += v2 * s0 + v3 * s1;  ed1 += v2 * d0 + v3 * d1;
        }
    }
    if (a_s) {
#pragma unroll
        for (int o = 1; o <= 2; o <<= 1) {
            es0 += __shfl_xor_sync(0xffffffffu, es0, o);
            ed0 += __shfl_xor_sync(0xffffffffu, ed0, o);
            es1 += __shfl_xor_sync(0xffffffffu, es1, o);
            ed1 += __shfl_xor_sync(0xffffffffu, ed1, o);
        }
        if (tig == 0) {
            if (r0 < n) { g_es[r0] = es0; g_ed[r0] = ed0; }
            if (r1 < n) { g_es[r1] = es1; g_ed[r1] = ed1; }
        }
    }
}

// ---------------- phase A: edge-parallel exp precompute ----------------
__global__ void k_edge_ex(int e) {
    int i = blockIdx.x * blockDim.x + threadIdx.x;
    if (i >= e) return;
    int s = g_col[i];
    int d = g_row[i];
    g_ex[i] = __expf(leaky(g_es[s] + g_ed[d]));
}

// ---------------- phase B: warp-per-node weighted gather ----------------
// Per edge: uniform contiguous LDG ex[k] + LDG.64 feature + fma2. No exp, no
// dependent col->es chain. 8x unroll keeps 8 feature loads in flight.
__global__ void __launch_bounds__(256) k_agg(const float* __restrict__ bias,
                                             float* __restrict__ out, int n, int mode) {
    int w = (blockIdx.x * blockDim.x + threadIdx.x) >> 5;
    if (w >= n) return;
    int lane = threadIdx.x & 31;
    int beg = g_rowptr[w], end = g_rowptr[w + 1];

    float ex_self = __expf(leaky(g_es[w] + g_ed[w]));
    float2 hv = *reinterpret_cast<const float2*>(g_lin + (size_t)w * 64 + 2 * lane);
    ull acc = 0ull;
    fma2(acc, pack2(ex_self, ex_self), pack2(hv.x, hv.y));
    float den = ex_self;

    int k = beg;
    for (; k + 8 <= end; k += 8) {
        float e0 = g_ex[k],     e1 = g_ex[k + 1], e2 = g_ex[k + 2], e3 = g_ex[k + 3];
        float e4 = g_ex[k + 4], e5 = g_ex[k + 5], e6 = g_ex[k + 6], e7 = g_ex[k + 7];
        int s0 = g_col[k],     s1 = g_col[k + 1], s2 = g_col[k + 2], s3 = g_col[k + 3];
        int s4 = g_col[k + 4], s5 = g_col[k + 5], s6 = g_col[k + 6], s7 = g_col[k + 7];
        float2 v0 = *reinterpret_cast<const float2*>(g_lin + (size_t)s0 * 64 + 2 * lane);
        float2 v1 = *reinterpret_cast<const float2*>(g_lin + (size_t)s1 * 64 + 2 * lane);
        float2 v2 = *reinterpret_cast<const float2*>(g_lin + (size_t)s2 * 64 + 2 * lane);
        float2 v3 = *reinterpret_cast<const float2*>(g_lin + (size_t)s3 * 64 + 2 * lane);
        float2 v4 = *reinterpret_cast<const float2*>(g_lin + (size_t)s4 * 64 + 2 * lane);
        float2 v5 = *reinterpret_cast<const float2*>(g_lin + (size_t)s5 * 64 + 2 * lane);
        float2 v6 = *reinterpret_cast<const float2*>(g_lin + (size_t)s6 * 64 + 2 * lane);
        float2 v7 = *reinterpret_cast<const float2*>(g_lin + (size_t)s7 * 64 + 2 * lane);
        den += (e0 + e1 + e2 + e3) + (e4 + e5 + e6 + e7);
        fma2(acc, pack2(e0, e0), pack2(v0.x, v0.y));
        fma2(acc, pack2(e1, e1), pack2(v1.x, v1.y));
        fma2(acc, pack2(e2, e2), pack2(v2.x, v2.y));
        fma2(acc, pack2(e3, e3), pack2(v3.x, v3.y));
        fma2(acc, pack2(e4, e4), pack2(v4.x, v4.y));
        fma2(acc, pack2(e5, e5), pack2(v5.x, v5.y));
        fma2(acc, pack2(e6, e6), pack2(v6.x, v6.y));
        fma2(acc, pack2(e7, e7), pack2(v7.x, v7.y));
    }
    for (; k < end; k++) {
        float ex = g_ex[k];
        int s = g_col[k];
        float2 v = *reinterpret_cast<const float2*>(g_lin + (size_t)s * 64 + 2 * lane);
        den += ex;
        fma2(acc, pack2(ex, ex), pack2(v.x, v.y));
    }

    float inv = 1.f / (den + 1e-16f);
    float2 bvec = *reinterpret_cast<const float2*>(bias + 2 * lane);
    float2 av = unpack2(acc);
    float o0 = av.x * inv + bvec.x;
    float o1 = av.y * inv + bvec.y;
    if (mode == 0) {
        o0 = fmaxf(o0, 0.f);
        o1 = fmaxf(o1, 0.f);
    } else {
        float ss = o0 * o0 + o1 * o1;
#pragma unroll
        for (int o = 16; o; o >>= 1) ss += __shfl_xor_sync(0xffffffffu, ss, o);
        float nrm = fmaxf(sqrtf(ss), 1e-12f);
        o0 /= nrm; o1 /= nrm;
    }
    *reinterpret_cast<float2*>(out + (size_t)w * 64 + 2 * lane) = make_float2(o0, o1);
}

// ---------------- launch ----------------
extern "C" void kernel_launch(void* const* d_in, const int* in_sizes, int n_in,
                              void* d_out, int out_size) {
    const float* x     = (const float*)d_in[0];
    const int*   src   = (const int*)d_in[1];
    const int*   dst   = (const int*)d_in[2];
    const float* lin_w = (const float*)d_in[3];
    const float* lin_b = (const float*)d_in[4];
    const float* W[3]  = { (const float*)d_in[5],  (const float*)d_in[9],  (const float*)d_in[13] };
    const float* AS[3] = { (const float*)d_in[6],  (const float*)d_in[10], (const float*)d_in[14] };
    const float* AD[3] = { (const float*)d_in[7],  (const float*)d_in[11], (const float*)d_in[15] };
    const float* BI[3] = { (const float*)d_in[8],  (const float*)d_in[12], (const float*)d_in[16] };

    const int n = in_sizes[0] / 256;   // 100000
    const int e = in_sizes[1];         // 1280000

    float *hA, *hB, *lin, *Wp, *bp;
    int *degp;
    cudaGetSymbolAddress((void**)&hA,   g_hA);
    cudaGetSymbolAddress((void**)&hB,   g_hB);
    cudaGetSymbolAddress((void**)&lin,  g_lin);
    cudaGetSymbolAddress((void**)&degp, g_deg);
    cudaGetSymbolAddress((void**)&Wp,   g_Wp);
    cudaGetSymbolAddress((void**)&bp,   g_bp);

    // Side stream + events for CSR/GEMM overlap (created once; capture-safe fork/join)
    static cudaStream_t s2 = nullptr;
    static cudaEvent_t evFork = nullptr, evJoin = nullptr;
    if (!s2) {
        cudaStreamCreate(&s2);
        cudaEventCreateWithFlags(&evFork, cudaEventDisableTiming);
        cudaEventCreateWithFlags(&evJoin, cudaEventDisableTiming);
    }

    const int TB = 256;
    dim3 gE((e + TB - 1) / TB);
    dim3 gG((n + 127) / 128);
    dim3 gW((n + 7) / 8);

    // Fork: CSR build on s2, concurrent with prep + fused gemm1 on main stream.
    cudaEventRecord(evFork, 0);
    cudaStreamWaitEvent(s2, evFork, 0);

    cudaMemsetAsync(degp, 0, (size_t)n * sizeof(int), s2);
    k_hist<<<gE, TB, 0, s2>>>(dst, e);
    k_scan<<<1, 1024, 0, s2>>>(n);
    k_scatter<<<gE, TB, 0, s2>>>(src, dst, e);
    cudaEventRecord(evJoin, s2);

    // Fused pre+layer1 weights: Wp = lin_w @ W1, bp = lin_b @ W1
    k_prep<<<64, 256>>>(lin_w, W[0], lin_b);

    // Layer 1: lin = x @ Wp + bp (K=256), fused es/ed — independent of CSR
    k_gemm_tc<<<gG, TB>>>(x, Wp, bp, AS[0], AD[0], lin, n, 256);

    // Join: edge kernels need the CSR
    cudaStreamWaitEvent(0, evJoin, 0);
    k_edge_ex<<<gE, TB>>>(e);
    k_agg<<<gW, TB>>>(BI[0], hB, n, 0);

    // Layer 2
    k_gemm_tc<<<gG, TB>>>(hB, W[1], nullptr, AS[1], AD[1], lin, n, 64);
    k_edge_ex<<<gE, TB>>>(e);
    k_agg<<<gW, TB>>>(BI[1], hA, n, 0);

    // Layer 3 (+ row L2 normalize) -> d_out
    k_gemm_tc<<<gG, TB>>>(hA, W[2], nullptr, AS[2], AD[2], lin, n, 64);
    k_edge_ex<<<gE, TB>>>(e);
    k_agg<<<gW, TB>>>(BI[2], (float*)d_out, n, 1);
}

// round 17
// speedup vs baseline: 1.4529x; 1.0013x over previous
#include <cuda_runtime.h>
#include <math.h>

// N=100000, E=1280000, IN_D=256, FEAT=HID=OUT=64
#define NMAX 100000
#define EMAX 1280000
#define NEG_SLOPE 0.2f

// ---------------- scratch ----------------
__device__ float g_hB[NMAX * 64];
__device__ float g_hA[NMAX * 64];
__device__ float g_lin[NMAX * 64];
__device__ float g_es[NMAX];
__device__ float g_ed[NMAX];
__device__ float g_ex[EMAX];          // per-CSR-slot exp(leaky(.))
__device__ int   g_deg[NMAX];
__device__ int   g_cur[NMAX];
__device__ int   g_rowptr[NMAX + 1];
__device__ int   g_col[EMAX];         // src per CSR slot
__device__ int   g_row[EMAX];         // dst per CSR slot
__device__ float g_Wp[256 * 64];      // lin_w @ W1
__device__ float g_bp[64];            // lin_b @ W1

__device__ __forceinline__ float leaky(float x) { return x > 0.f ? x : NEG_SLOPE * x; }

typedef unsigned long long ull;
__device__ __forceinline__ void fma2(ull& d, ull a, ull b) {
    asm("fma.rn.f32x2 %0, %1, %2, %0;" : "+l"(d) : "l"(a), "l"(b));
}
__device__ __forceinline__ ull pack2(float lo, float hi) {
    ull r;
    asm("mov.b64 %0, {%1, %2};" : "=l"(r) : "f"(lo), "f"(hi));
    return r;
}
__device__ __forceinline__ float2 unpack2(ull v) {
    float2 f;
    asm("mov.b64 {%0, %1}, %2;" : "=f"(f.x), "=f"(f.y) : "l"(v));
    return f;
}

// TF32 helpers
__device__ __forceinline__ unsigned to_tf32(float x) {
    unsigned r;
    asm("cvt.rna.tf32.f32 %0, %1;" : "=r"(r) : "f"(x));
    return r;
}
__device__ __forceinline__ void mma_tf32(float& c0, float& c1, float& c2, float& c3,
                                         unsigned a0, unsigned a1, unsigned a2, unsigned a3,
                                         unsigned b0, unsigned b1) {
    asm("mma.sync.aligned.m16n8k8.row.col.f32.tf32.tf32.f32 "
        "{%0,%1,%2,%3}, {%4,%5,%6,%7}, {%8,%9}, {%0,%1,%2,%3};"
        : "+f"(c0), "+f"(c1), "+f"(c2), "+f"(c3)
        : "r"(a0), "r"(a1), "r"(a2), "r"(a3), "r"(b0), "r"(b1));
}

// ---------------- CSR build ----------------
__global__ void k_hist(const int* __restrict__ dst, int e) {
    int i = blockIdx.x * blockDim.x + threadIdx.x;
    if (i < e) atomicAdd(&g_deg[dst[i]], 1);
}
__global__ void k_scan(int n) {
    __shared__ int s[1024];
    int t = threadIdx.x;
    int chunk = (n + 1023) >> 10;
    int beg = t * chunk;
    int end = beg + chunk; if (end > n) end = n;
    int sum = 0;
    for (int i = beg; i < end; i++) sum += g_deg[i];
    s[t] = sum;
    __syncthreads();
    for (int off = 1; off < 1024; off <<= 1) {
        int v = 0;
        if (t >= off) v = s[t - off];
        __syncthreads();
        if (t >= off) s[t] += v;
        __syncthreads();
    }
    int prefix = (t == 0) ? 0 : s[t - 1];
    for (int i = beg; i < end; i++) {
        g_rowptr[i] = prefix;
        prefix += g_deg[i];
        g_cur[i] = 0;
    }
    if (t == 1023) g_rowptr[n] = s[1023];
}
__global__ void k_scatter(const int* __restrict__ src, const int* __restrict__ dst, int e) {
    int i = blockIdx.x * blockDim.x + threadIdx.x;
    if (i >= e) return;
    int d = dst[i];
    int pos = g_rowptr[d] + atomicAdd(&g_cur[d], 1);
    g_col[pos] = src[i];
    g_row[pos] = d;
}

// ---------------- prep: Wp = lin_w @ W1, bp = lin_b @ W1 ----------------
__global__ void k_prep(const float* __restrict__ lin_w, const float* __restrict__ w1,
                       const float* __restrict__ lin_b) {
    int j = blockIdx.x * blockDim.x + threadIdx.x;  // 0..16383
    if (j >= 256 * 64) return;
    int col = j & 63, row = j >> 6;
    float s = 0.f;
#pragma unroll 8
    for (int k = 0; k < 64; k++) s += lin_w[row * 64 + k] * w1[k * 64 + col];
    g_Wp[row * 64 + col] = s;
    if (row == 0) {
        float b = 0.f;
#pragma unroll 8
        for (int k = 0; k < 64; k++) b += lin_b[k] * w1[k * 64 + col];
        g_bp[col] = b;
    }
}

// ---------------- TF32 tensor-core GEMM: C[n x 64] = A[n x K] @ B[K x 64] ----------------
#define ASTR 68
#define BSTR 68
__global__ void __launch_bounds__(256) k_gemm_tc(
        const float* __restrict__ A, const float* __restrict__ B,
        const float* __restrict__ bias,
        const float* __restrict__ a_s, const float* __restrict__ a_d,
        float* __restrict__ C, int n, int K) {
    __shared__ unsigned As[128 * ASTR];  // tf32 bits, As[m][k]
    __shared__ unsigned Bs[64 * BSTR];   // tf32 bits, Bs[k][j]
    const int tid = threadIdx.x;
    const int warp = tid >> 5;
    const int lane = tid & 31;
    const int g = lane >> 2;
    const int tig = lane & 3;
    const int row0 = blockIdx.x * 128;
    const int mrow = warp * 16;

    float c[8][4];
#pragma unroll
    for (int nt = 0; nt < 8; nt++)
#pragma unroll
        for (int i = 0; i < 4; i++) c[nt][i] = 0.f;

    for (int k0 = 0; k0 < K; k0 += 64) {
#pragma unroll
        for (int l = 0; l < 8; l++) {
            int idx = tid + l * 256;
            int m = idx >> 4;
            int kq = idx & 15;
            int grow = row0 + m;
            float4 v = make_float4(0.f, 0.f, 0.f, 0.f);
            if (grow < n)
                v = *reinterpret_cast<const float4*>(A + (size_t)grow * K + k0 + kq * 4);
            uint4 u = make_uint4(to_tf32(v.x), to_tf32(v.y), to_tf32(v.z), to_tf32(v.w));
            *reinterpret_cast<uint4*>(&As[m * ASTR + kq * 4]) = u;
        }
#pragma unroll
        for (int l = 0; l < 4; l++) {
            int idx = tid + l * 256;
            int k = idx >> 4;
            int jq = idx & 15;
            float4 v = *reinterpret_cast<const float4*>(B + (size_t)(k0 + k) * 64 + jq * 4);
            uint4 u = make_uint4(to_tf32(v.x), to_tf32(v.y), to_tf32(v.z), to_tf32(v.w));
            *reinterpret_cast<uint4*>(&Bs[k * BSTR + jq * 4]) = u;
        }
        __syncthreads();

        unsigned a[8][4];
#pragma unroll
        for (int ks = 0; ks < 8; ks++) {
            int kk = ks * 8;
            a[ks][0] = As[(mrow + g)     * ASTR + kk + tig];
            a[ks][1] = As[(mrow + g + 8) * ASTR + kk + tig];
            a[ks][2] = As[(mrow + g)     * ASTR + kk + tig + 4];
            a[ks][3] = As[(mrow + g + 8) * ASTR + kk + tig + 4];
        }
#pragma unroll
        for (int nt = 0; nt < 8; nt++) {
#pragma unroll
            for (int ks = 0; ks < 8; ks++) {
                unsigned b0 = Bs[(ks * 8 + tig)     * BSTR + nt * 8 + g];
                unsigned b1 = Bs[(ks * 8 + tig + 4) * BSTR + nt * 8 + g];
                mma_tf32(c[nt][0], c[nt][1], c[nt][2], c[nt][3],
                         a[ks][0], a[ks][1], a[ks][2], a[ks][3], b0, b1);
            }
        }
        __syncthreads();
    }

    int r0 = row0 + mrow + g;
    int r1 = r0 + 8;
    float es0 = 0.f, ed0 = 0.f, es1 = 0.f, ed1 = 0.f;
#pragma unroll
    for (int nt = 0; nt < 8; nt++) {
        int col = nt * 8 + 2 * tig;
        float b0v = 0.f, b1v = 0.f;
        if (bias) { b0v = bias[col]; b1v = bias[col + 1]; }
        float v0 = c[nt][0] + b0v, v1 = c[nt][1] + b1v;
        float v2 = c[nt][2] + b0v, v3 = c[nt][3] + b1v;
        if (r0 < n)
            *reinterpret_cast<float2*>(C + (size_t)r0 * 64 + col) = make_float2(v0, v1);
        if (r1 < n)
            *reinterpret_cast<float2*>(C + (size_t)r1 * 64 + col) = make_float2(v2, v3);
        if (a_s) {
            float s0 = a_s[col], s1 = a_s[col + 1];
            float d0 = a_d[col], d1 = a_d[col + 1];
            es0 += v0 * s0 + v1 * s1;  ed0 += v0 * d0 + v1 * d1;
            es1 += v2 * s0 + v3 * s1;  ed1 += v2 * d0 + v3 * d1;
        }
    }
    if (a_s) {
#pragma unroll
        for (int o = 1; o <= 2; o <<= 1) {
            es0 += __shfl_xor_sync(0xffffffffu, es0, o);
            ed0 += __shfl_xor_sync(0xffffffffu, ed0, o);
            es1 += __shfl_xor_sync(0xffffffffu, es1, o);
            ed1 += __shfl_xor_sync(0xffffffffu, ed1, o);
        }
        if (tig == 0) {
            if (r0 < n) { g_es[r0] = es0; g_ed[r0] = ed0; }
            if (r1 < n) { g_es[r1] = es1; g_ed[r1] = ed1; }
        }
    }
}

// ---------------- phase A: edge-parallel exp precompute ----------------
__global__ void k_edge_ex(int e) {
    int i = blockIdx.x * blockDim.x + threadIdx.x;
    if (i >= e) return;
    int s = g_col[i];
    int d = g_row[i];
    g_ex[i] = __expf(leaky(g_es[s] + g_ed[d]));
}

// ---------------- phase B: warp-per-node weighted gather ----------------
// Per edge: uniform contiguous LDG ex[k] + LDG.64 feature + fma2. No exp, no
// dependent col->es chain. 8x unroll keeps 8 feature loads in flight.
__global__ void __launch_bounds__(256) k_agg(const float* __restrict__ bias,
                                             float* __restrict__ out, int n, int mode) {
    int w = (blockIdx.x * blockDim.x + threadIdx.x) >> 5;
    if (w >= n) return;
    int lane = threadIdx.x & 31;
    int beg = g_rowptr[w], end = g_rowptr[w + 1];

    float ex_self = __expf(leaky(g_es[w] + g_ed[w]));
    float2 hv = *reinterpret_cast<const float2*>(g_lin + (size_t)w * 64 + 2 * lane);
    ull acc = 0ull;
    fma2(acc, pack2(ex_self, ex_self), pack2(hv.x, hv.y));
    float den = ex_self;

    int k = beg;
    for (; k + 8 <= end; k += 8) {
        float e0 = g_ex[k],     e1 = g_ex[k + 1], e2 = g_ex[k + 2], e3 = g_ex[k + 3];
        float e4 = g_ex[k + 4], e5 = g_ex[k + 5], e6 = g_ex[k + 6], e7 = g_ex[k + 7];
        int s0 = g_col[k],     s1 = g_col[k + 1], s2 = g_col[k + 2], s3 = g_col[k + 3];
        int s4 = g_col[k + 4], s5 = g_col[k + 5], s6 = g_col[k + 6], s7 = g_col[k + 7];
        float2 v0 = *reinterpret_cast<const float2*>(g_lin + (size_t)s0 * 64 + 2 * lane);
        float2 v1 = *reinterpret_cast<const float2*>(g_lin + (size_t)s1 * 64 + 2 * lane);
        float2 v2 = *reinterpret_cast<const float2*>(g_lin + (size_t)s2 * 64 + 2 * lane);
        float2 v3 = *reinterpret_cast<const float2*>(g_lin + (size_t)s3 * 64 + 2 * lane);
        float2 v4 = *reinterpret_cast<const float2*>(g_lin + (size_t)s4 * 64 + 2 * lane);
        float2 v5 = *reinterpret_cast<const float2*>(g_lin + (size_t)s5 * 64 + 2 * lane);
        float2 v6 = *reinterpret_cast<const float2*>(g_lin + (size_t)s6 * 64 + 2 * lane);
        float2 v7 = *reinterpret_cast<const float2*>(g_lin + (size_t)s7 * 64 + 2 * lane);
        den += (e0 + e1 + e2 + e3) + (e4 + e5 + e6 + e7);
        fma2(acc, pack2(e0, e0), pack2(v0.x, v0.y));
        fma2(acc, pack2(e1, e1), pack2(v1.x, v1.y));
        fma2(acc, pack2(e2, e2), pack2(v2.x, v2.y));
        fma2(acc, pack2(e3, e3), pack2(v3.x, v3.y));
        fma2(acc, pack2(e4, e4), pack2(v4.x, v4.y));
        fma2(acc, pack2(e5, e5), pack2(v5.x, v5.y));
        fma2(acc, pack2(e6, e6), pack2(v6.x, v6.y));
        fma2(acc, pack2(e7, e7), pack2(v7.x, v7.y));
    }
    for (; k < end; k++) {
        float ex = g_ex[k];
        int s = g_col[k];
        float2 v = *reinterpret_cast<const float2*>(g_lin + (size_t)s * 64 + 2 * lane);
        den += ex;
        fma2(acc, pack2(ex, ex), pack2(v.x, v.y));
    }

    float inv = 1.f / (den + 1e-16f);
    float2 bvec = *reinterpret_cast<const float2*>(bias + 2 * lane);
    float2 av = unpack2(acc);
    float o0 = av.x * inv + bvec.x;
    float o1 = av.y * inv + bvec.y;
    if (mode == 0) {
        o0 = fmaxf(o0, 0.f);
        o1 = fmaxf(o1, 0.f);
    } else {
        float ss = o0 * o0 + o1 * o1;
#pragma unroll
        for (int o = 16; o; o >>= 1) ss += __shfl_xor_sync(0xffffffffu, ss, o);
        float nrm = fmaxf(sqrtf(ss), 1e-12f);
        o0 /= nrm; o1 /= nrm;
    }
    *reinterpret_cast<float2*>(out + (size_t)w * 64 + 2 * lane) = make_float2(o0, o1);
}

// ---------------- launch ----------------
extern "C" void kernel_launch(void* const* d_in, const int* in_sizes, int n_in,
                              void* d_out, int out_size) {
    const float* x     = (const float*)d_in[0];
    const int*   src   = (const int*)d_in[1];
    const int*   dst   = (const int*)d_in[2];
    const float* lin_w = (const float*)d_in[3];
    const float* lin_b = (const float*)d_in[4];
    const float* W[3]  = { (const float*)d_in[5],  (const float*)d_in[9],  (const float*)d_in[13] };
    const float* AS[3] = { (const float*)d_in[6],  (const float*)d_in[10], (const float*)d_in[14] };
    const float* AD[3] = { (const float*)d_in[7],  (const float*)d_in[11], (const float*)d_in[15] };
    const float* BI[3] = { (const float*)d_in[8],  (const float*)d_in[12], (const float*)d_in[16] };

    const int n = in_sizes[0] / 256;   // 100000
    const int e = in_sizes[1];         // 1280000

    float *hA, *hB, *lin, *Wp, *bp;
    int *degp;
    cudaGetSymbolAddress((void**)&hA,   g_hA);
    cudaGetSymbolAddress((void**)&hB,   g_hB);
    cudaGetSymbolAddress((void**)&lin,  g_lin);
    cudaGetSymbolAddress((void**)&degp, g_deg);
    cudaGetSymbolAddress((void**)&Wp,   g_Wp);
    cudaGetSymbolAddress((void**)&bp,   g_bp);

    // Side stream + events for CSR/GEMM overlap (created once; capture-safe fork/join)
    static cudaStream_t s2 = nullptr;
    static cudaEvent_t evFork = nullptr, evJoin = nullptr;
    if (!s2) {
        cudaStreamCreate(&s2);
        cudaEventCreateWithFlags(&evFork, cudaEventDisableTiming);
        cudaEventCreateWithFlags(&evJoin, cudaEventDisableTiming);
    }

    const int TB = 256;
    dim3 gE((e + TB - 1) / TB);
    dim3 gG((n + 127) / 128);
    dim3 gW((n + 7) / 8);

    // Fork: CSR build on s2, concurrent with prep + fused gemm1 on main stream.
    cudaEventRecord(evFork, 0);
    cudaStreamWaitEvent(s2, evFork, 0);

    cudaMemsetAsync(degp, 0, (size_t)n * sizeof(int), s2);
    k_hist<<<gE, TB, 0, s2>>>(dst, e);
    k_scan<<<1, 1024, 0, s2>>>(n);
    k_scatter<<<gE, TB, 0, s2>>>(src, dst, e);
    cudaEventRecord(evJoin, s2);

    // Fused pre+layer1 weights: Wp = lin_w @ W1, bp = lin_b @ W1
    k_prep<<<64, 256>>>(lin_w, W[0], lin_b);

    // Layer 1: lin = x @ Wp + bp (K=256), fused es/ed — independent of CSR
    k_gemm_tc<<<gG, TB>>>(x, Wp, bp, AS[0], AD[0], lin, n, 256);

    // Join: edge kernels need the CSR
    cudaStreamWaitEvent(0, evJoin, 0);
    k_edge_ex<<<gE, TB>>>(e);
    k_agg<<<gW, TB>>>(BI[0], hB, n, 0);

    // Layer 2
    k_gemm_tc<<<gG, TB>>>(hB, W[1], nullptr, AS[1], AD[1], lin, n, 64);
    k_edge_ex<<<gE, TB>>>(e);
    k_agg<<<gW, TB>>>(BI[1], hA, n, 0);

    // Layer 3 (+ row L2 normalize) -> d_out
    k_gemm_tc<<<gG, TB>>>(hA, W[2], nullptr, AS[2], AD[2], lin, n, 64);
    k_edge_ex<<<gE, TB>>>(e);
    k_agg<<<gW, TB>>>(BI[2], (float*)d_out, n, 1);
}